// round 3
// baseline (speedup 1.0000x reference)
#include <cuda_runtime.h>
#include <cstdint>

#define Nn 8192
#define Dd 1024
#define MARGINc 1.0f
#define EPSc 1e-6f

// ---------------- scratch (static __device__ globals, allowed) ----------------
__device__ float g_sq[Nn];
__device__ float g_Dmat[(size_t)Nn * Nn];          // 256 MB distance matrix
__device__ unsigned long long g_pos[Nn];           // packed (dist_bits<<32)|~j
__device__ float g_dp[Nn];
__device__ int   g_posidx[Nn];
__device__ int   g_negidx[Nn];
__device__ float g_rowloss[Nn];

// ---------------- K1: row squared norms + reset g_pos ----------------
__global__ __launch_bounds__(256) void sq_kernel(const float* __restrict__ emb) {
    int row  = blockIdx.x * 8 + (threadIdx.x >> 5);
    int lane = threadIdx.x & 31;
    const float* p = emb + (size_t)row * Dd;
    float s = 0.f;
    #pragma unroll
    for (int k = lane * 4; k < Dd; k += 128) {
        float4 v = *(const float4*)(p + k);
        s += v.x * v.x + v.y * v.y + v.z * v.z + v.w * v.w;
    }
    #pragma unroll
    for (int off = 16; off; off >>= 1) s += __shfl_xor_sync(0xffffffffu, s, off);
    if (lane == 0) { g_sq[row] = s; g_pos[row] = 0ULL; }
}

// ---------------- K2: fp32 tiled GEMM -> distances + hardest-positive ----------------
// Block tile 128x128, K-step 8, 256 threads, 8x8 micro-tile per thread.
#define BM 128
#define BN 128
#define BK 8
#define PADW 132

__global__ __launch_bounds__(256) void gemm_pos_kernel(const float* __restrict__ emb,
                                                       const int*   __restrict__ tgt) {
    __shared__ __align__(16) float As[BK][PADW];
    __shared__ __align__(16) float Bs[BK][PADW];

    const int rowBase = blockIdx.y * BM;
    const int colBase = blockIdx.x * BN;
    const int tid = threadIdx.x;
    const int tx = tid & 15;
    const int ty = tid >> 4;

    float acc[8][8];
    #pragma unroll
    for (int r = 0; r < 8; r++)
        #pragma unroll
        for (int c = 0; c < 8; c++) acc[r][c] = 0.f;

    const int lr = tid >> 1;          // 0..127 : tile row
    const int lk = (tid & 1) * 4;     // 0 or 4 : k offset
    const float* Aptr = emb + (size_t)(rowBase + lr) * Dd + lk;
    const float* Bptr = emb + (size_t)(colBase + lr) * Dd + lk;

    for (int k0 = 0; k0 < Dd; k0 += BK) {
        float4 av = *(const float4*)(Aptr + k0);
        float4 bv = *(const float4*)(Bptr + k0);
        __syncthreads();
        As[lk + 0][lr] = av.x; As[lk + 1][lr] = av.y;
        As[lk + 2][lr] = av.z; As[lk + 3][lr] = av.w;
        Bs[lk + 0][lr] = bv.x; Bs[lk + 1][lr] = bv.y;
        Bs[lk + 2][lr] = bv.z; Bs[lk + 3][lr] = bv.w;
        __syncthreads();
        #pragma unroll
        for (int kk = 0; kk < BK; kk++) {
            float4 a0 = *(const float4*)&As[kk][ty * 8];
            float4 a1 = *(const float4*)&As[kk][ty * 8 + 4];
            float4 b0 = *(const float4*)&Bs[kk][tx * 8];
            float4 b1 = *(const float4*)&Bs[kk][tx * 8 + 4];
            float a[8] = {a0.x, a0.y, a0.z, a0.w, a1.x, a1.y, a1.z, a1.w};
            float b[8] = {b0.x, b0.y, b0.z, b0.w, b1.x, b1.y, b1.z, b1.w};
            #pragma unroll
            for (int r = 0; r < 8; r++)
                #pragma unroll
                for (int c = 0; c < 8; c++)
                    acc[r][c] = fmaf(a[r], b[c], acc[r][c]);
        }
    }

    // epilogue: distances, store row-major, fused hardest-positive argmax
    const int gi0 = rowBase + ty * 8;
    const int gj0 = colBase + tx * 8;
    float sqi[8], sqj[8];
    int   ci[8],  cj[8];
    #pragma unroll
    for (int r = 0; r < 8; r++) { sqi[r] = g_sq[gi0 + r]; ci[r] = tgt[gi0 + r]; }
    #pragma unroll
    for (int c = 0; c < 8; c++) { sqj[c] = g_sq[gj0 + c]; cj[c] = tgt[gj0 + c]; }

    #pragma unroll
    for (int r = 0; r < 8; r++) {
        const int gi = gi0 + r;
        float dv[8];
        unsigned long long best = 0ULL;
        #pragma unroll
        for (int c = 0; c < 8; c++) {
            float d2 = sqi[r] + sqj[c] - 2.f * acc[r][c];
            float d  = sqrtf(fmaxf(d2, 0.f));
            dv[c] = d;
            const int gj = gj0 + c;
            if (ci[r] == cj[c] && gi != gj) {
                unsigned long long key =
                    ((unsigned long long)__float_as_uint(d) << 32) | (unsigned)(~gj);
                if (key > best) best = key;
            }
        }
        float* outp = &g_Dmat[(size_t)gi * Nn + gj0];
        *(float4*)(outp)     = make_float4(dv[0], dv[1], dv[2], dv[3]);
        *(float4*)(outp + 4) = make_float4(dv[4], dv[5], dv[6], dv[7]);
        // reduce across the 16 tx lanes sharing this row block (stays within half-warp)
        #pragma unroll
        for (int off = 8; off >= 1; off >>= 1) {
            unsigned long long o = __shfl_xor_sync(0xffffffffu, best, off);
            if (o > best) best = o;
        }
        if (tx == 0 && best) atomicMax(&g_pos[gi], best);
    }
}

// ---------------- K3: unpack hardest positive ----------------
__global__ void pos_extract_kernel() {
    int i = blockIdx.x * 256 + threadIdx.x;
    unsigned long long key = g_pos[i];
    if (key == 0ULL) { g_dp[i] = -1e9f; g_posidx[i] = 0; }  // no positive: match ref fallback
    else {
        g_dp[i]     = __uint_as_float((unsigned)(key >> 32));
        g_posidx[i] = (int)(~(unsigned)key);
    }
}

// ---------------- K4: semi-hard / hardest negative per row ----------------
__global__ __launch_bounds__(256) void neg_kernel(const int* __restrict__ tgt) {
    const int i   = blockIdx.x;
    const int cls = tgt[i];
    const float dp = g_dp[i];
    const float hi = dp + MARGINc;
    unsigned long long semi = ~0ULL, hard = ~0ULL;
    const float* row = &g_Dmat[(size_t)i * Nn];
    for (int j = threadIdx.x; j < Nn; j += 256) {
        if (tgt[j] != cls) {
            float d = row[j];
            unsigned long long key =
                ((unsigned long long)__float_as_uint(d) << 32) | (unsigned)j;
            if (key < hard) hard = key;
            if (d > dp && d < hi && key < semi) semi = key;
        }
    }
    __shared__ unsigned long long sS[256], sH[256];
    sS[threadIdx.x] = semi; sH[threadIdx.x] = hard;
    __syncthreads();
    for (int s = 128; s; s >>= 1) {
        if (threadIdx.x < s) {
            if (sS[threadIdx.x + s] < sS[threadIdx.x]) sS[threadIdx.x] = sS[threadIdx.x + s];
            if (sH[threadIdx.x + s] < sH[threadIdx.x]) sH[threadIdx.x] = sH[threadIdx.x + s];
        }
        __syncthreads();
    }
    if (threadIdx.x == 0) {
        unsigned long long k = (sS[0] != ~0ULL) ? sS[0] : sH[0];
        g_negidx[i] = (int)(unsigned)k;
    }
}

// ---------------- K5: per-row triplet loss (exact torch eps formula) ----------------
__global__ __launch_bounds__(256) void loss_kernel(const float* __restrict__ emb) {
    const int i = blockIdx.x;
    const float* a = emb + (size_t)i * Dd;
    const float* p = emb + (size_t)g_posidx[i] * Dd;
    const float* n = emb + (size_t)g_negidx[i] * Dd;
    const int k = threadIdx.x * 4;   // 256*4 = 1024 exactly
    float4 av = *(const float4*)(a + k);
    float4 pv = *(const float4*)(p + k);
    float4 nv = *(const float4*)(n + k);
    float sp = 0.f, sn = 0.f, d;
    d = av.x - pv.x + EPSc; sp += d * d;
    d = av.y - pv.y + EPSc; sp += d * d;
    d = av.z - pv.z + EPSc; sp += d * d;
    d = av.w - pv.w + EPSc; sp += d * d;
    d = av.x - nv.x + EPSc; sn += d * d;
    d = av.y - nv.y + EPSc; sn += d * d;
    d = av.z - nv.z + EPSc; sn += d * d;
    d = av.w - nv.w + EPSc; sn += d * d;

    __shared__ float ssp[256], ssn[256];
    ssp[threadIdx.x] = sp; ssn[threadIdx.x] = sn;
    __syncthreads();
    for (int s = 128; s; s >>= 1) {
        if (threadIdx.x < s) {
            ssp[threadIdx.x] += ssp[threadIdx.x + s];
            ssn[threadIdx.x] += ssn[threadIdx.x + s];
        }
        __syncthreads();
    }
    if (threadIdx.x == 0)
        g_rowloss[i] = fmaxf(sqrtf(ssp[0]) - sqrtf(ssn[0]) + MARGINc, 0.f);
}

// ---------------- K6: deterministic mean reduction ----------------
__global__ __launch_bounds__(1024) void final_kernel(float* __restrict__ out) {
    __shared__ float s[1024];
    const int t = threadIdx.x;
    float v = 0.f;
    #pragma unroll
    for (int b = 0; b < 8; b++) v += g_rowloss[t + b * 1024];
    s[t] = v;
    __syncthreads();
    for (int w = 512; w; w >>= 1) {
        if (t < w) s[t] += s[t + w];
        __syncthreads();
    }
    if (t == 0) out[0] = s[0] / (float)Nn;
}

// ---------------- launch ----------------
extern "C" void kernel_launch(void* const* d_in, const int* in_sizes, int n_in,
                              void* d_out, int out_size) {
    const float* emb = (const float*)d_in[0];
    const int*   tgt = (const int*)d_in[1];
    float* out = (float*)d_out;

    sq_kernel<<<Nn / 8, 256>>>(emb);
    dim3 grid(Nn / BN, Nn / BM);
    gemm_pos_kernel<<<grid, 256>>>(emb, tgt);
    pos_extract_kernel<<<Nn / 256, 256>>>();
    neg_kernel<<<Nn, 256>>>(tgt);
    loss_kernel<<<Nn, 256>>>(emb);
    final_kernel<<<1, 1024>>>(out);
}